// round 15
// baseline (speedup 1.0000x reference)
#include <cuda_runtime.h>
#include <cuda_bf16.h>
#include <cuda_fp16.h>
#include <math.h>

#define Lc   1024
#define Bc   2
#define Dc   1024
#define Hc   16
#define DHc  64
#define DFFc 4096
#define MEMc 1024
#define Tc   2048
#define HDc  (Hc*DHc)          // 1024
#define SCALEF 0.125f

// ---------------- scratch (device globals; no allocation) ----------------
__device__ __half g_c   [Tc*Bc*Dc];         // half concat(memory, x)
__device__ __half g_xr  [Lc*Bc*Dc];         // half x
__device__ __half g_per [Tc*Bc*Dc];         // half pos_emb
__device__ __half g_kv  [Tc*Bc*2*HDc];      // half kv proj
__device__ __half g_r   [Tc*Bc*HDc];        // half rel proj
__device__ __half g_qu  [Lc*Bc*HDc];        // half q + u
__device__ __half g_qv  [Lc*Bc*HDc];        // half q + v
__device__ __half g_Sac [67108864];         // [B*H, L, T] AC scores half; then probs in place
__device__ __half g_Sbd [67108864];         // [B*H, L, T] BD scores half (unshifted)
__device__ __half g_vec [Lc*Bc*HDc];        // half attention vec
__device__ float  g_res [Lc*Bc*Dc];         // x + attn_out (fp32)
__device__ float  g_out1[Lc*Bc*Dc];         // ln1 out (fp32 residual)
__device__ __half g_o1r [Lc*Bc*Dc];         // ln1 out half (GEMM A)
__device__ __half g_ff1 [Lc*Bc*DFFc];       // half relu(out1@W1+b1)
__device__ float  g_res2[Lc*Bc*Dc];         // out1 + ff (fp32)
// half transposed weights
__device__ __half g_WkvT[2*HDc*Dc];
__device__ __half g_WrelT[HDc*Dc];
__device__ __half g_WqT [HDc*Dc];
__device__ __half g_WoT [Dc*HDc];
__device__ __half g_W1T [DFFc*Dc];
__device__ __half g_W2T [Dc*DFFc];
__device__ __half g_vt  [Bc*Hc*DHc*Tc];     // v transposed: [b,h,d,t]

// ---------------- helpers ----------------
__device__ __forceinline__ void mma_f16(float c[4], const unsigned a[4], const unsigned b[2]) {
    asm volatile(
        "mma.sync.aligned.m16n8k16.row.col.f32.f16.f16.f32 "
        "{%0,%1,%2,%3}, {%4,%5,%6,%7}, {%8,%9}, {%0,%1,%2,%3};"
        : "+f"(c[0]), "+f"(c[1]), "+f"(c[2]), "+f"(c[3])
        : "r"(a[0]), "r"(a[1]), "r"(a[2]), "r"(a[3]), "r"(b[0]), "r"(b[1]));
}
__device__ __forceinline__ void cp16(void* smem, const void* gmem) {
    unsigned s = (unsigned)__cvta_generic_to_shared(smem);
    asm volatile("cp.async.ca.shared.global [%0], [%1], 16;" :: "r"(s), "l"(gmem));
}

// ---------------- elementwise producers (emit half) ----------------
__global__ void concat_kernel(const float* __restrict__ mem, const float* __restrict__ x,
                              __half* __restrict__ c) {
    int idx = blockIdx.x * 256 + threadIdx.x;
    if (idx < Tc*Bc*Dc)
        c[idx] = __float2half_rn((idx < MEMc*Bc*Dc) ? mem[idx] : x[idx - MEMc*Bc*Dc]);
}

__global__ void half_copy_kernel(const float* __restrict__ in, __half* __restrict__ out, int n) {
    int idx = blockIdx.x * 256 + threadIdx.x;
    if (idx < n) out[idx] = __float2half_rn(in[idx]);
}

// out[n][k] = half(in[k][n]); grid (N/32, K/32), block (32,8)
__global__ void transpose_kernel(const float* __restrict__ in, __half* __restrict__ out,
                                 int K, int N) {
    __shared__ float t[32][33];
    int n0 = blockIdx.x * 32, k0 = blockIdx.y * 32;
    int tx = threadIdx.x, ty = threadIdx.y;
    for (int r = ty; r < 32; r += 8)
        t[r][tx] = in[(size_t)(k0 + r) * N + n0 + tx];
    __syncthreads();
    for (int r = ty; r < 32; r += 8)
        out[(size_t)(n0 + r) * K + k0 + tx] = __float2half_rn(t[tx][r]);
}

// vt[b,h,d,t] = v[t,b,h,d] (kv already half); grid (T/32, DH/32, B*H)
__global__ void vtrans_kernel(const __half* __restrict__ kv, __half* __restrict__ vt) {
    __shared__ __half t[32][33];
    int b = blockIdx.z >> 4;
    int j0 = blockIdx.x * 32, d0 = blockIdx.y * 32;
    int tx = threadIdx.x, ty = threadIdx.y;
    int h = blockIdx.z & 15;
    const __half* in = kv + b * (2*HDc) + HDc + h * DHc;
    for (int r = ty; r < 32; r += 8)
        t[r][tx] = in[(size_t)(j0 + r) * (Bc*2*HDc) + d0 + tx];
    __syncthreads();
    __half* out = vt + (size_t)blockIdx.z * DHc * Tc;
    for (int r = ty; r < 32; r += 8)
        out[(size_t)(d0 + r) * Tc + j0 + tx] = t[tx][r];
}

// ---------------- FP16 tensor-core GEMM (mma.sync m16n8k16, fp32 accumulate) ----------------
// D[m][n] = sum_k A[m][k]*Bt[n][k]  (both K-major half). M%128==0, N%BN==0, K%32==0.
// lda/ldb/ldc and batch strides in ELEMENTS. Smem rows padded to 80B (conflict-free b32 loads).
// mode: 0 none; 1 skip fully-masked causal tiles; 2 skip BD tiles shift never reads;
//       3 clamp K tiles to causal limit. outHalf: C is __half*, else float*.
template<int BN>
__global__ __launch_bounds__(256, 2)
void f16_gemm(const __half* __restrict__ A, const __half* __restrict__ Bt,
              void* __restrict__ Cv,
              int M, int N, int K, int lda, int ldb, int ldc,
              int Hdim, long long sAb, long long sAh, long long sBb, long long sBh,
              long long sCb, long long sCh,
              const float* __restrict__ bias, const float* __restrict__ resid,
              int ldr, int doRelu, int outHalf, int mode,
              __half* __restrict__ C2, const float* __restrict__ bias2)
{
    constexpr int NT = BN / 32;            // n-subtiles (of 8) per warp
    constexpr int ASTAGE = 128 * 80;       // bytes per A stage
    constexpr int BSTAGE = BN * 80;
    extern __shared__ char sm[];
    char* smA = sm;
    char* smB = sm + 2 * ASTAGE;

    int bm = blockIdx.y * 128, bn = blockIdx.x * BN;
    if (mode == 1 && bn >= bm + 128 + MEMc) return;            // fully masked
    if (mode == 2 && bn + BN + bm + 127 < Lc) return;          // shift never reads here

    int z = blockIdx.z, bz = z / Hdim, hz = z % Hdim;
    A  += bz * sAb + hz * sAh;
    Bt += bz * sBb + hz * sBh;

    int tid = threadIdx.x, warp = tid >> 5, lane = tid & 31;
    int qid = lane >> 2, tq = lane & 3;
    int wm = (warp >> 2) * 64;
    int wn = (warp & 3) * (NT * 8);

    auto load_stage = [&](int st, int k0) {
        char* as = smA + st * ASTAGE;
#pragma unroll
        for (int i = 0; i < 2; i++) {
            int idx = tid + i * 256;               // 0..511
            int row = idx >> 2, c = idx & 3;
            cp16(as + row * 80 + c * 16, A + (size_t)(bm + row) * lda + k0 + c * 8);
        }
        char* bs = smB + st * BSTAGE;
#pragma unroll
        for (int i = 0; i < BN / 64; i++) {
            int idx = tid + i * 256;
            int row = idx >> 2, c = idx & 3;
            cp16(bs + row * 80 + c * 16, Bt + (size_t)(bn + row) * ldb + k0 + c * 8);
        }
        asm volatile("cp.async.commit_group;");
    };

    float acc[4][NT][4];
#pragma unroll
    for (int mi = 0; mi < 4; mi++)
#pragma unroll
        for (int ni = 0; ni < NT; ni++)
#pragma unroll
            for (int e = 0; e < 4; e++) acc[mi][ni][e] = 0.f;

    int KT = K >> 5;
    if (mode == 3) {
        int kt2 = (bm + 128 + MEMc) >> 5;
        if (kt2 < KT) KT = kt2;
    }
    load_stage(0, 0);

    for (int kt = 0; kt < KT; kt++) {
        if (kt + 1 < KT) {
            load_stage((kt + 1) & 1, (kt + 1) * 32);
            asm volatile("cp.async.wait_group 1;");
        } else {
            asm volatile("cp.async.wait_group 0;");
        }
        __syncthreads();
        const char* as = smA + (kt & 1) * ASTAGE;
        const char* bs = smB + (kt & 1) * BSTAGE;

#pragma unroll
        for (int s = 0; s < 2; s++) {              // two k16 steps per 32-k chunk
            unsigned af[4][4];
#pragma unroll
            for (int mi = 0; mi < 4; mi++) {
                const char* base = as + (wm + mi * 16 + qid) * 80 + s * 32 + tq * 4;
                af[mi][0] = *(const unsigned*)(base);
                af[mi][1] = *(const unsigned*)(base + 8 * 80);
                af[mi][2] = *(const unsigned*)(base + 16);
                af[mi][3] = *(const unsigned*)(base + 8 * 80 + 16);
            }
            unsigned bf[NT][2];
#pragma unroll
            for (int ni = 0; ni < NT; ni++) {
                const char* bb = bs + (wn + ni * 8 + qid) * 80 + s * 32 + tq * 4;
                bf[ni][0] = *(const unsigned*)(bb);
                bf[ni][1] = *(const unsigned*)(bb + 16);
            }
#pragma unroll
            for (int mi = 0; mi < 4; mi++)
#pragma unroll
                for (int ni = 0; ni < NT; ni++)
                    mma_f16(acc[mi][ni], af[mi], bf[ni]);
        }
        __syncthreads();
    }

    // ---- epilogue ----
    float*  Cf = (float*)Cv;
    __half* Ch = (__half*)Cv;
    if (outHalf) Ch += bz * sCb + hz * sCh; else Cf += bz * sCb + hz * sCh;
#pragma unroll
    for (int mi = 0; mi < 4; mi++) {
        int r0 = bm + wm + mi * 16 + qid;
#pragma unroll
        for (int ni = 0; ni < NT; ni++) {
            int c0 = bn + wn + ni * 8 + 2 * tq;
#pragma unroll
            for (int h = 0; h < 2; h++) {
                int rr = r0 + h * 8;
                float vx = acc[mi][ni][2*h], vy = acc[mi][ni][2*h+1];
                float ax = vx, ay = vy;
                if (bias)  { vx += bias[c0]; vy += bias[c0+1]; }
                if (resid) {
                    const float* rp = resid + (size_t)rr * ldr + c0;
                    vx += rp[0]; vy += rp[1];
                }
                if (doRelu) { vx = fmaxf(vx, 0.f); vy = fmaxf(vy, 0.f); }
                if (outHalf)
                    *(__half2*)(Ch + (size_t)rr * ldc + c0) = __floats2half2_rn(vx, vy);
                else
                    *(float2*)(Cf + (size_t)rr * ldc + c0) = make_float2(vx, vy);
                if (C2)
                    *(__half2*)(C2 + (size_t)rr * ldc + c0) =
                        __floats2half2_rn(ax + bias2[c0], ay + bias2[c0+1]);
            }
        }
    }
}

// ---------------- fused masked softmax + attn_matrix (rel-shift folded) ----------------
// grid (Lc); loops z=0..31 internally. Probs written in place (half) up to the per-tile
// causal bound (exactly the region the vec GEMM's K-clamp reads); attn = mean over z.
__global__ __launch_bounds__(256)
void softmax_fused_kernel(__half* __restrict__ P, const __half* __restrict__ BD,
                          float* __restrict__ attn)
{
    int i = blockIdx.x, tid = threadIdx.x;
    int valid = i + MEMc + 1;
    int shift = Lc - 1 - i;
    int bound = (i & ~127) + 128 + MEMc;          // vec GEMM reads cols [0, bound)
    if (bound > Tc) bound = Tc;

    float at[8];
#pragma unroll
    for (int t = 0; t < 8; t++) at[t] = 0.f;

    __shared__ float red[8], red2[8];

    for (int z = 0; z < Bc*Hc; z++) {
        __half*       ac = P  + ((size_t)z * Lc + i) * Tc;
        const __half* bd = BD + ((size_t)z * Lc + i) * Tc;

        float s[8];
        float mx = -1e30f;
#pragma unroll
        for (int t = 0; t < 8; t++) {
            int j = tid + 256 * t;
            if (j < valid) {
                s[t] = (__half2float(ac[j]) + __half2float(bd[j + shift])) * SCALEF;
                mx = fmaxf(mx, s[t]);
            } else s[t] = -1e30f;
        }
        for (int o = 16; o > 0; o >>= 1) mx = fmaxf(mx, __shfl_xor_sync(~0u, mx, o));
        if ((tid & 31) == 0) red[tid >> 5] = mx;
        __syncthreads();
        mx = red[0];
#pragma unroll
        for (int w = 1; w < 8; w++) mx = fmaxf(mx, red[w]);

        float sum = 0.f;
#pragma unroll
        for (int t = 0; t < 8; t++) {
            float e = (s[t] > -1e29f) ? __expf(s[t] - mx) : 0.f;
            s[t] = e; sum += e;
        }
        for (int o = 16; o > 0; o >>= 1) sum += __shfl_xor_sync(~0u, sum, o);
        if ((tid & 31) == 0) red2[tid >> 5] = sum;
        __syncthreads();
        sum = 0.f;
#pragma unroll
        for (int w = 0; w < 8; w++) sum += red2[w];
        float inv = 1.f / sum;
#pragma unroll
        for (int t = 0; t < 8; t++) {
            int j = tid + 256 * t;
            float p = s[t] * inv;
            if (j < bound) ac[j] = __float2half_rn(p);
            at[t] += p;
        }
        __syncthreads();   // red/red2 reused next z
    }

#pragma unroll
    for (int t = 0; t < 8; t++) {
        int j = tid + 256 * t;
        attn[(size_t)i * Tc + j] = (j < valid) ? at[t] * (1.f / (Bc*Hc)) : 0.f;
    }
}

// ---------------- layernorm (fp32 out + optional half second output) ----------------
__global__ __launch_bounds__(256)
void ln_kernel(const float* __restrict__ X, float* __restrict__ Y, __half* __restrict__ Yr,
               const float* __restrict__ g, const float* __restrict__ b)
{
    int row = blockIdx.x;
    const float* xr = X + (size_t)row * Dc;
    float*       yr = Y + (size_t)row * Dc;
    __shared__ float r1[256], r2[256];
    int tid = threadIdx.x;
    float s1 = 0.f, s2 = 0.f;
    for (int d = tid; d < Dc; d += 256) {
        float v = xr[d];
        s1 += v; s2 += v*v;
    }
    r1[tid] = s1; r2[tid] = s2; __syncthreads();
    for (int s = 128; s > 0; s >>= 1) {
        if (tid < s) { r1[tid] += r1[tid+s]; r2[tid] += r2[tid+s]; }
        __syncthreads();
    }
    float mean = r1[0] * (1.f/Dc);
    float var  = r2[0] * (1.f/Dc) - mean*mean;
    float rinv = rsqrtf(var + 1e-5f);
    for (int d = tid; d < Dc; d += 256) {
        float v = (xr[d] - mean) * rinv * g[d] + b[d];
        yr[d] = v;
        if (Yr) Yr[(size_t)row * Dc + d] = __float2half_rn(v);
    }
}

// ---------------- host ----------------
template<int BN>
static void hg(const __half* A, const __half* Bt, void* C,
               int M, int N, int K, int lda, int ldb, int ldc,
               int Z, int Hdim,
               long long sAb, long long sAh, long long sBb, long long sBh,
               long long sCb, long long sCh,
               const float* bias, const float* resid, int ldr, int doRelu, int outHalf,
               int mode = 0,
               __half* C2 = nullptr, const float* bias2 = nullptr)
{
    size_t smB = (size_t)(2 * 128 * 80 + 2 * BN * 80);
    dim3 g(N / BN, M / 128, Z);
    f16_gemm<BN><<<g, 256, smB>>>(A, Bt, C, M, N, K, lda, ldb, ldc, Hdim,
                                  sAb, sAh, sBb, sBh, sCb, sCh,
                                  bias, resid, ldr, doRelu, outHalf, mode, C2, bias2);
}

extern "C" void kernel_launch(void* const* d_in, const int* in_sizes, int n_in,
                              void* d_out, int out_size)
{
    int o = (in_sizes[5] == 1048576) ? 0 : 1;

    const float* x    = (const float*)d_in[0];
    const float* pe   = (const float*)d_in[1];
    const float* pu   = (const float*)d_in[2];
    const float* pv   = (const float*)d_in[3];
    const float* mem  = (const float*)d_in[4];
    const float* Wq   = (const float*)d_in[5  + o];
    const float* Wkv  = (const float*)d_in[6  + o];
    const float* Wo   = (const float*)d_in[7  + o];
    const float* Wrel = (const float*)d_in[8  + o];
    const float* g1   = (const float*)d_in[9  + o];
    const float* b1l  = (const float*)d_in[10 + o];
    const float* W1   = (const float*)d_in[11 + o];
    const float* b1   = (const float*)d_in[12 + o];
    const float* W2   = (const float*)d_in[13 + o];
    const float* b2   = (const float*)d_in[14 + o];
    const float* g2   = (const float*)d_in[15 + o];
    const float* b2l  = (const float*)d_in[16 + o];

    __half *p_c, *p_xr, *p_per, *p_kv, *p_r, *p_qu, *p_qv, *p_Sac, *p_Sbd, *p_vec,
           *p_o1r, *p_ff1, *p_WkvT, *p_WrelT, *p_WqT, *p_WoT, *p_W1T, *p_W2T, *p_vt;
    float  *p_res, *p_out1, *p_res2;
    cudaGetSymbolAddress((void**)&p_c,    g_c);
    cudaGetSymbolAddress((void**)&p_xr,   g_xr);
    cudaGetSymbolAddress((void**)&p_per,  g_per);
    cudaGetSymbolAddress((void**)&p_kv,   g_kv);
    cudaGetSymbolAddress((void**)&p_r,    g_r);
    cudaGetSymbolAddress((void**)&p_qu,   g_qu);
    cudaGetSymbolAddress((void**)&p_qv,   g_qv);
    cudaGetSymbolAddress((void**)&p_Sac,  g_Sac);
    cudaGetSymbolAddress((void**)&p_Sbd,  g_Sbd);
    cudaGetSymbolAddress((void**)&p_vec,  g_vec);
    cudaGetSymbolAddress((void**)&p_res,  g_res);
    cudaGetSymbolAddress((void**)&p_out1, g_out1);
    cudaGetSymbolAddress((void**)&p_o1r,  g_o1r);
    cudaGetSymbolAddress((void**)&p_ff1,  g_ff1);
    cudaGetSymbolAddress((void**)&p_res2, g_res2);
    cudaGetSymbolAddress((void**)&p_WkvT, g_WkvT);
    cudaGetSymbolAddress((void**)&p_WrelT,g_WrelT);
    cudaGetSymbolAddress((void**)&p_WqT,  g_WqT);
    cudaGetSymbolAddress((void**)&p_WoT,  g_WoT);
    cudaGetSymbolAddress((void**)&p_W1T,  g_W1T);
    cudaGetSymbolAddress((void**)&p_W2T,  g_W2T);
    cudaGetSymbolAddress((void**)&p_vt,   g_vt);

    cudaFuncSetAttribute(f16_gemm<128>, cudaFuncAttributeMaxDynamicSharedMemorySize,
                         2 * 128 * 80 + 2 * 128 * 80);
    cudaFuncSetAttribute(f16_gemm<64>,  cudaFuncAttributeMaxDynamicSharedMemorySize,
                         2 * 128 * 80 + 2 * 64 * 80);

    float* out_main = (float*)d_out;
    float* out_attn = out_main + (size_t)Lc*Bc*Dc;

    dim3 tb(32, 8);

    // 0) producers: half concat / copies / weight transposes
    concat_kernel<<<(Tc*Bc*Dc + 255)/256, 256>>>(mem, x, p_c);
    half_copy_kernel<<<(Lc*Bc*Dc + 255)/256, 256>>>(x,  p_xr,  Lc*Bc*Dc);
    half_copy_kernel<<<(Tc*Bc*Dc + 255)/256, 256>>>(pe, p_per, Tc*Bc*Dc);
    transpose_kernel<<<dim3(2*HDc/32, Dc/32),  tb>>>(Wkv,  p_WkvT,  Dc, 2*HDc);
    transpose_kernel<<<dim3(HDc/32,   Dc/32),  tb>>>(Wrel, p_WrelT, Dc, HDc);
    transpose_kernel<<<dim3(HDc/32,   Dc/32),  tb>>>(Wq,   p_WqT,   Dc, HDc);
    transpose_kernel<<<dim3(Dc/32,    HDc/32), tb>>>(Wo,   p_WoT,   HDc, Dc);
    transpose_kernel<<<dim3(DFFc/32,  Dc/32),  tb>>>(W1,   p_W1T,   Dc, DFFc);
    transpose_kernel<<<dim3(Dc/32,    DFFc/32),tb>>>(W2,   p_W2T,   DFFc, Dc);

    // 1) kv = c @ Wkv  (half out)
    hg<128>(p_c, p_WkvT, p_kv, Tc*Bc, 2*HDc, Dc, Dc, Dc, 2*HDc,
            1, 1, 0,0,0,0,0,0, nullptr, nullptr, 0, 0, 1);
    // 2) r = pos_emb @ Wrel (half out)
    hg<128>(p_per, p_WrelT, p_r, Tc*Bc, HDc, Dc, Dc, Dc, HDc,
            1, 1, 0,0,0,0,0,0, nullptr, nullptr, 0, 0, 1);
    // 3) qu = x@Wq + u ; qv = x@Wq + v  (dual half outputs, BN=64: 256 CTAs)
    hg<64>(p_xr, p_WqT, p_qu, Lc*Bc, HDc, Dc, Dc, Dc, HDc,
           1, 1, 0,0,0,0,0,0, pu, nullptr, 0, 0, 1, 0, p_qv, pv);

    // v transpose
    vtrans_kernel<<<dim3(Tc/32, DHc/32, Bc*Hc), tb>>>(p_kv, p_vt);

    // 4) AC = qu @ k^T (half out, mode 1: skip fully-masked tiles)
    hg<128>(p_qu, p_kv, p_Sac, Lc, Tc, DHc, Bc*HDc, Bc*2*HDc, Tc,
            Bc*Hc, Hc,
            (long long)HDc, (long long)DHc,
            (long long)2*HDc, (long long)DHc,
            (long long)Hc*Lc*Tc, (long long)Lc*Tc,
            nullptr, nullptr, 0, 0, 1, 1);
    // 5) BD = qv @ r^T (half out, mode 2: skip tiles the shift never reads)
    hg<128>(p_qv, p_r, p_Sbd, Lc, Tc, DHc, Bc*HDc, Bc*HDc, Tc,
            Bc*Hc, Hc,
            (long long)HDc, (long long)DHc,
            (long long)HDc, (long long)DHc,
            (long long)Hc*Lc*Tc, (long long)Lc*Tc,
            nullptr, nullptr, 0, 0, 1, 2);

    // 6) fused softmax + attn matrix (probs in place, trimmed writes)
    softmax_fused_kernel<<<Lc, 256>>>(p_Sac, p_Sbd, out_attn);

    // 7) vec = probs @ v  (half probs, lda = Tc; BN=64; mode 3 K-clamp)
    hg<64>(p_Sac, p_vt, p_vec, Lc, DHc, Tc, Tc, Tc, Bc*HDc,
           Bc*Hc, Hc,
           (long long)Hc*Lc*Tc, (long long)Lc*Tc,
           (long long)Hc*DHc*Tc, (long long)DHc*Tc,
           (long long)HDc, (long long)DHc,
           nullptr, nullptr, 0, 0, 1, 3);

    // 8) res = x + vec @ Wo  (fp32 out, BN=64: 256 CTAs)
    hg<64>(p_vec, p_WoT, p_res, Lc*Bc, Dc, HDc, HDc, HDc, Dc,
           1, 1, 0,0,0,0,0,0, nullptr, x, Dc, 0, 0);

    // 9) LN1 (fp32 + half outputs)
    ln_kernel<<<Lc*Bc, 256>>>(p_res, p_out1, p_o1r, g1, b1l);

    // 10) ff1 = relu(out1 @ W1 + b1) (half out)
    hg<128>(p_o1r, p_W1T, p_ff1, Lc*Bc, DFFc, Dc, Dc, Dc, DFFc,
            1, 1, 0,0,0,0,0,0, b1, nullptr, 0, 1, 1);

    // 11) res2 = out1 + ff1 @ W2 + b2 (fp32 out, BN=64: 256 CTAs)
    hg<64>(p_ff1, p_W2T, p_res2, Lc*Bc, Dc, DFFc, DFFc, DFFc, Dc,
           1, 1, 0,0,0,0,0,0, b2, p_out1, Dc, 0, 0);

    // 12) LN2 -> final output
    ln_kernel<<<Lc*Bc, 256>>>(p_res2, out_main, nullptr, g2, b2l);
}

// round 16
// speedup vs baseline: 1.0352x; 1.0352x over previous
#include <cuda_runtime.h>
#include <cuda_bf16.h>
#include <cuda_fp16.h>
#include <math.h>

#define Lc   1024
#define Bc   2
#define Dc   1024
#define Hc   16
#define DHc  64
#define DFFc 4096
#define MEMc 1024
#define Tc   2048
#define HDc  (Hc*DHc)          // 1024
#define SCALEF 0.125f

// ---------------- scratch (device globals; no allocation) ----------------
__device__ __half g_c   [Tc*Bc*Dc];         // half concat(memory, x)
__device__ __half g_xr  [Lc*Bc*Dc];         // half x
__device__ __half g_per [Tc*Bc*Dc];         // half pos_emb
__device__ __half g_kv  [Tc*Bc*2*HDc];      // half kv proj
__device__ __half g_r   [Tc*Bc*HDc];        // half rel proj
__device__ __half g_qu  [Lc*Bc*HDc];        // half q + u
__device__ __half g_qv  [Lc*Bc*HDc];        // half q + v
__device__ __half g_Sac [67108864];         // [B*H, L, T] AC scores half; then probs in place
__device__ __half g_Sbd [67108864];         // [B*H, L, T] BD scores half (unshifted)
__device__ __half g_vec [Lc*Bc*HDc];        // half attention vec
__device__ float  g_res [Lc*Bc*Dc];         // x + attn_out (fp32)
__device__ float  g_out1[Lc*Bc*Dc];         // ln1 out (fp32 residual)
__device__ __half g_o1r [Lc*Bc*Dc];         // ln1 out half (GEMM A)
__device__ __half g_ff1 [Lc*Bc*DFFc];       // half relu(out1@W1+b1)
__device__ float  g_res2[Lc*Bc*Dc];         // out1 + ff (fp32)
// half transposed weights
__device__ __half g_WkvT[2*HDc*Dc];
__device__ __half g_WrelT[HDc*Dc];
__device__ __half g_WqT [HDc*Dc];
__device__ __half g_WoT [Dc*HDc];
__device__ __half g_W1T [DFFc*Dc];
__device__ __half g_W2T [Dc*DFFc];
__device__ __half g_vt  [Bc*Hc*DHc*Tc];     // v transposed: [b,h,d,t]

// ---------------- helpers ----------------
__device__ __forceinline__ void mma_f16(float c[4], const unsigned a[4], const unsigned b[2]) {
    asm volatile(
        "mma.sync.aligned.m16n8k16.row.col.f32.f16.f16.f32 "
        "{%0,%1,%2,%3}, {%4,%5,%6,%7}, {%8,%9}, {%0,%1,%2,%3};"
        : "+f"(c[0]), "+f"(c[1]), "+f"(c[2]), "+f"(c[3])
        : "r"(a[0]), "r"(a[1]), "r"(a[2]), "r"(a[3]), "r"(b[0]), "r"(b[1]));
}
__device__ __forceinline__ void cp16(void* smem, const void* gmem) {
    unsigned s = (unsigned)__cvta_generic_to_shared(smem);
    asm volatile("cp.async.ca.shared.global [%0], [%1], 16;" :: "r"(s), "l"(gmem));
}

// ---------------- elementwise producers (emit half) ----------------
__global__ void concat_kernel(const float* __restrict__ mem, const float* __restrict__ x,
                              __half* __restrict__ c) {
    int idx = blockIdx.x * 256 + threadIdx.x;
    if (idx < Tc*Bc*Dc)
        c[idx] = __float2half_rn((idx < MEMc*Bc*Dc) ? mem[idx] : x[idx - MEMc*Bc*Dc]);
}

__global__ void half_copy_kernel(const float* __restrict__ in, __half* __restrict__ out, int n) {
    int idx = blockIdx.x * 256 + threadIdx.x;
    if (idx < n) out[idx] = __float2half_rn(in[idx]);
}

// out[n][k] = half(in[k][n]); grid (N/32, K/32), block (32,8)
__global__ void transpose_kernel(const float* __restrict__ in, __half* __restrict__ out,
                                 int K, int N) {
    __shared__ float t[32][33];
    int n0 = blockIdx.x * 32, k0 = blockIdx.y * 32;
    int tx = threadIdx.x, ty = threadIdx.y;
    for (int r = ty; r < 32; r += 8)
        t[r][tx] = in[(size_t)(k0 + r) * N + n0 + tx];
    __syncthreads();
    for (int r = ty; r < 32; r += 8)
        out[(size_t)(n0 + r) * K + k0 + tx] = __float2half_rn(t[tx][r]);
}

// vt[b,h,d,t] = v[t,b,h,d] (kv already half); grid (T/32, DH/32, B*H)
__global__ void vtrans_kernel(const __half* __restrict__ kv, __half* __restrict__ vt) {
    __shared__ __half t[32][33];
    int b = blockIdx.z >> 4;
    int j0 = blockIdx.x * 32, d0 = blockIdx.y * 32;
    int tx = threadIdx.x, ty = threadIdx.y;
    int h = blockIdx.z & 15;
    const __half* in = kv + b * (2*HDc) + HDc + h * DHc;
    for (int r = ty; r < 32; r += 8)
        t[r][tx] = in[(size_t)(j0 + r) * (Bc*2*HDc) + d0 + tx];
    __syncthreads();
    __half* out = vt + (size_t)blockIdx.z * DHc * Tc;
    for (int r = ty; r < 32; r += 8)
        out[(size_t)(d0 + r) * Tc + j0 + tx] = t[tx][r];
}

// ---------------- FP16 tensor-core GEMM (mma.sync m16n8k16, fp32 accumulate) ----------------
// D[m][n] = sum_k A[m][k]*Bt[n][k]  (both K-major half). M%128==0, N%BN==0, K%32==0.
// lda/ldb/ldc and batch strides in ELEMENTS. Smem rows padded to 80B (conflict-free b32 loads).
// mode: 0 none; 1 skip fully-masked causal tiles; 2 skip BD tiles shift never reads;
//       3 clamp K tiles to causal limit. outHalf: C is __half*, else float*.
template<int BN>
__global__ __launch_bounds__(256, 2)
void f16_gemm(const __half* __restrict__ A, const __half* __restrict__ Bt,
              void* __restrict__ Cv,
              int M, int N, int K, int lda, int ldb, int ldc,
              int Hdim, long long sAb, long long sAh, long long sBb, long long sBh,
              long long sCb, long long sCh,
              const float* __restrict__ bias, const float* __restrict__ resid,
              int ldr, int doRelu, int outHalf, int mode,
              __half* __restrict__ C2, const float* __restrict__ bias2)
{
    constexpr int NT = BN / 32;            // n-subtiles (of 8) per warp
    constexpr int ASTAGE = 128 * 80;       // bytes per A stage
    constexpr int BSTAGE = BN * 80;
    extern __shared__ char sm[];
    char* smA = sm;
    char* smB = sm + 2 * ASTAGE;

    int bm = blockIdx.y * 128, bn = blockIdx.x * BN;
    if (mode == 1 && bn >= bm + 128 + MEMc) return;            // fully masked
    if (mode == 2 && bn + BN + bm + 127 < Lc) return;          // shift never reads here

    int z = blockIdx.z, bz = z / Hdim, hz = z % Hdim;
    A  += bz * sAb + hz * sAh;
    Bt += bz * sBb + hz * sBh;

    int tid = threadIdx.x, warp = tid >> 5, lane = tid & 31;
    int qid = lane >> 2, tq = lane & 3;
    int wm = (warp >> 2) * 64;
    int wn = (warp & 3) * (NT * 8);

    auto load_stage = [&](int st, int k0) {
        char* as = smA + st * ASTAGE;
#pragma unroll
        for (int i = 0; i < 2; i++) {
            int idx = tid + i * 256;               // 0..511
            int row = idx >> 2, c = idx & 3;
            cp16(as + row * 80 + c * 16, A + (size_t)(bm + row) * lda + k0 + c * 8);
        }
        char* bs = smB + st * BSTAGE;
#pragma unroll
        for (int i = 0; i < BN / 64; i++) {
            int idx = tid + i * 256;
            int row = idx >> 2, c = idx & 3;
            cp16(bs + row * 80 + c * 16, Bt + (size_t)(bn + row) * ldb + k0 + c * 8);
        }
        asm volatile("cp.async.commit_group;");
    };

    float acc[4][NT][4];
#pragma unroll
    for (int mi = 0; mi < 4; mi++)
#pragma unroll
        for (int ni = 0; ni < NT; ni++)
#pragma unroll
            for (int e = 0; e < 4; e++) acc[mi][ni][e] = 0.f;

    int KT = K >> 5;
    if (mode == 3) {
        int kt2 = (bm + 128 + MEMc) >> 5;
        if (kt2 < KT) KT = kt2;
    }
    load_stage(0, 0);

    for (int kt = 0; kt < KT; kt++) {
        if (kt + 1 < KT) {
            load_stage((kt + 1) & 1, (kt + 1) * 32);
            asm volatile("cp.async.wait_group 1;");
        } else {
            asm volatile("cp.async.wait_group 0;");
        }
        __syncthreads();
        const char* as = smA + (kt & 1) * ASTAGE;
        const char* bs = smB + (kt & 1) * BSTAGE;

#pragma unroll
        for (int s = 0; s < 2; s++) {              // two k16 steps per 32-k chunk
            unsigned af[4][4];
#pragma unroll
            for (int mi = 0; mi < 4; mi++) {
                const char* base = as + (wm + mi * 16 + qid) * 80 + s * 32 + tq * 4;
                af[mi][0] = *(const unsigned*)(base);
                af[mi][1] = *(const unsigned*)(base + 8 * 80);
                af[mi][2] = *(const unsigned*)(base + 16);
                af[mi][3] = *(const unsigned*)(base + 8 * 80 + 16);
            }
            unsigned bf[NT][2];
#pragma unroll
            for (int ni = 0; ni < NT; ni++) {
                const char* bb = bs + (wn + ni * 8 + qid) * 80 + s * 32 + tq * 4;
                bf[ni][0] = *(const unsigned*)(bb);
                bf[ni][1] = *(const unsigned*)(bb + 16);
            }
#pragma unroll
            for (int mi = 0; mi < 4; mi++)
#pragma unroll
                for (int ni = 0; ni < NT; ni++)
                    mma_f16(acc[mi][ni], af[mi], bf[ni]);
        }
        __syncthreads();
    }

    // ---- epilogue ----
    float*  Cf = (float*)Cv;
    __half* Ch = (__half*)Cv;
    if (outHalf) Ch += bz * sCb + hz * sCh; else Cf += bz * sCb + hz * sCh;
#pragma unroll
    for (int mi = 0; mi < 4; mi++) {
        int r0 = bm + wm + mi * 16 + qid;
#pragma unroll
        for (int ni = 0; ni < NT; ni++) {
            int c0 = bn + wn + ni * 8 + 2 * tq;
#pragma unroll
            for (int h = 0; h < 2; h++) {
                int rr = r0 + h * 8;
                float vx = acc[mi][ni][2*h], vy = acc[mi][ni][2*h+1];
                float ax = vx, ay = vy;
                if (bias)  { vx += bias[c0]; vy += bias[c0+1]; }
                if (resid) {
                    const float* rp = resid + (size_t)rr * ldr + c0;
                    vx += rp[0]; vy += rp[1];
                }
                if (doRelu) { vx = fmaxf(vx, 0.f); vy = fmaxf(vy, 0.f); }
                if (outHalf)
                    *(__half2*)(Ch + (size_t)rr * ldc + c0) = __floats2half2_rn(vx, vy);
                else
                    *(float2*)(Cf + (size_t)rr * ldc + c0) = make_float2(vx, vy);
                if (C2)
                    *(__half2*)(C2 + (size_t)rr * ldc + c0) =
                        __floats2half2_rn(ax + bias2[c0], ay + bias2[c0+1]);
            }
        }
    }
}

// ---------------- fused masked softmax + attn_matrix (rel-shift folded) ----------------
// grid (Lc); loops z=0..31 internally. Probs written in place (half) up to the per-tile
// causal bound (exactly the region the vec GEMM's K-clamp reads); attn = mean over z.
__global__ __launch_bounds__(256)
void softmax_fused_kernel(__half* __restrict__ P, const __half* __restrict__ BD,
                          float* __restrict__ attn)
{
    int i = blockIdx.x, tid = threadIdx.x;
    int valid = i + MEMc + 1;
    int shift = Lc - 1 - i;
    int bound = (i & ~127) + 128 + MEMc;          // vec GEMM reads cols [0, bound)
    if (bound > Tc) bound = Tc;

    float at[8];
#pragma unroll
    for (int t = 0; t < 8; t++) at[t] = 0.f;

    __shared__ float red[8], red2[8];

    for (int z = 0; z < Bc*Hc; z++) {
        __half*       ac = P  + ((size_t)z * Lc + i) * Tc;
        const __half* bd = BD + ((size_t)z * Lc + i) * Tc;

        float s[8];
        float mx = -1e30f;
#pragma unroll
        for (int t = 0; t < 8; t++) {
            int j = tid + 256 * t;
            if (j < valid) {
                s[t] = (__half2float(ac[j]) + __half2float(bd[j + shift])) * SCALEF;
                mx = fmaxf(mx, s[t]);
            } else s[t] = -1e30f;
        }
        for (int o = 16; o > 0; o >>= 1) mx = fmaxf(mx, __shfl_xor_sync(~0u, mx, o));
        if ((tid & 31) == 0) red[tid >> 5] = mx;
        __syncthreads();
        mx = red[0];
#pragma unroll
        for (int w = 1; w < 8; w++) mx = fmaxf(mx, red[w]);

        float sum = 0.f;
#pragma unroll
        for (int t = 0; t < 8; t++) {
            float e = (s[t] > -1e29f) ? __expf(s[t] - mx) : 0.f;
            s[t] = e; sum += e;
        }
        for (int o = 16; o > 0; o >>= 1) sum += __shfl_xor_sync(~0u, sum, o);
        if ((tid & 31) == 0) red2[tid >> 5] = sum;
        __syncthreads();
        sum = 0.f;
#pragma unroll
        for (int w = 0; w < 8; w++) sum += red2[w];
        float inv = 1.f / sum;
#pragma unroll
        for (int t = 0; t < 8; t++) {
            int j = tid + 256 * t;
            float p = s[t] * inv;
            if (j < bound) ac[j] = __float2half_rn(p);
            at[t] += p;
        }
        __syncthreads();   // red/red2 reused next z
    }

#pragma unroll
    for (int t = 0; t < 8; t++) {
        int j = tid + 256 * t;
        attn[(size_t)i * Tc + j] = (j < valid) ? at[t] * (1.f / (Bc*Hc)) : 0.f;
    }
}

// ---------------- layernorm (fp32 out + optional half second output) ----------------
__global__ __launch_bounds__(256)
void ln_kernel(const float* __restrict__ X, float* __restrict__ Y, __half* __restrict__ Yr,
               const float* __restrict__ g, const float* __restrict__ b)
{
    int row = blockIdx.x;
    const float* xr = X + (size_t)row * Dc;
    float*       yr = Y + (size_t)row * Dc;
    __shared__ float r1[256], r2[256];
    int tid = threadIdx.x;
    float s1 = 0.f, s2 = 0.f;
    for (int d = tid; d < Dc; d += 256) {
        float v = xr[d];
        s1 += v; s2 += v*v;
    }
    r1[tid] = s1; r2[tid] = s2; __syncthreads();
    for (int s = 128; s > 0; s >>= 1) {
        if (tid < s) { r1[tid] += r1[tid+s]; r2[tid] += r2[tid+s]; }
        __syncthreads();
    }
    float mean = r1[0] * (1.f/Dc);
    float var  = r2[0] * (1.f/Dc) - mean*mean;
    float rinv = rsqrtf(var + 1e-5f);
    for (int d = tid; d < Dc; d += 256) {
        float v = (xr[d] - mean) * rinv * g[d] + b[d];
        yr[d] = v;
        if (Yr) Yr[(size_t)row * Dc + d] = __float2half_rn(v);
    }
}

// ---------------- host ----------------
template<int BN>
static void hg(const __half* A, const __half* Bt, void* C,
               int M, int N, int K, int lda, int ldb, int ldc,
               int Z, int Hdim,
               long long sAb, long long sAh, long long sBb, long long sBh,
               long long sCb, long long sCh,
               const float* bias, const float* resid, int ldr, int doRelu, int outHalf,
               int mode = 0,
               __half* C2 = nullptr, const float* bias2 = nullptr)
{
    size_t smB = (size_t)(2 * 128 * 80 + 2 * BN * 80);
    dim3 g(N / BN, M / 128, Z);
    f16_gemm<BN><<<g, 256, smB>>>(A, Bt, C, M, N, K, lda, ldb, ldc, Hdim,
                                  sAb, sAh, sBb, sBh, sCb, sCh,
                                  bias, resid, ldr, doRelu, outHalf, mode, C2, bias2);
}

extern "C" void kernel_launch(void* const* d_in, const int* in_sizes, int n_in,
                              void* d_out, int out_size)
{
    int o = (in_sizes[5] == 1048576) ? 0 : 1;

    const float* x    = (const float*)d_in[0];
    const float* pe   = (const float*)d_in[1];
    const float* pu   = (const float*)d_in[2];
    const float* pv   = (const float*)d_in[3];
    const float* mem  = (const float*)d_in[4];
    const float* Wq   = (const float*)d_in[5  + o];
    const float* Wkv  = (const float*)d_in[6  + o];
    const float* Wo   = (const float*)d_in[7  + o];
    const float* Wrel = (const float*)d_in[8  + o];
    const float* g1   = (const float*)d_in[9  + o];
    const float* b1l  = (const float*)d_in[10 + o];
    const float* W1   = (const float*)d_in[11 + o];
    const float* b1   = (const float*)d_in[12 + o];
    const float* W2   = (const float*)d_in[13 + o];
    const float* b2   = (const float*)d_in[14 + o];
    const float* g2   = (const float*)d_in[15 + o];
    const float* b2l  = (const float*)d_in[16 + o];

    __half *p_c, *p_xr, *p_per, *p_kv, *p_r, *p_qu, *p_qv, *p_Sac, *p_Sbd, *p_vec,
           *p_o1r, *p_ff1, *p_WkvT, *p_WrelT, *p_WqT, *p_WoT, *p_W1T, *p_W2T, *p_vt;
    float  *p_res, *p_out1, *p_res2;
    cudaGetSymbolAddress((void**)&p_c,    g_c);
    cudaGetSymbolAddress((void**)&p_xr,   g_xr);
    cudaGetSymbolAddress((void**)&p_per,  g_per);
    cudaGetSymbolAddress((void**)&p_kv,   g_kv);
    cudaGetSymbolAddress((void**)&p_r,    g_r);
    cudaGetSymbolAddress((void**)&p_qu,   g_qu);
    cudaGetSymbolAddress((void**)&p_qv,   g_qv);
    cudaGetSymbolAddress((void**)&p_Sac,  g_Sac);
    cudaGetSymbolAddress((void**)&p_Sbd,  g_Sbd);
    cudaGetSymbolAddress((void**)&p_vec,  g_vec);
    cudaGetSymbolAddress((void**)&p_res,  g_res);
    cudaGetSymbolAddress((void**)&p_out1, g_out1);
    cudaGetSymbolAddress((void**)&p_o1r,  g_o1r);
    cudaGetSymbolAddress((void**)&p_ff1,  g_ff1);
    cudaGetSymbolAddress((void**)&p_res2, g_res2);
    cudaGetSymbolAddress((void**)&p_WkvT, g_WkvT);
    cudaGetSymbolAddress((void**)&p_WrelT,g_WrelT);
    cudaGetSymbolAddress((void**)&p_WqT,  g_WqT);
    cudaGetSymbolAddress((void**)&p_WoT,  g_WoT);
    cudaGetSymbolAddress((void**)&p_W1T,  g_W1T);
    cudaGetSymbolAddress((void**)&p_W2T,  g_W2T);
    cudaGetSymbolAddress((void**)&p_vt,   g_vt);

    cudaFuncSetAttribute(f16_gemm<128>, cudaFuncAttributeMaxDynamicSharedMemorySize,
                         2 * 128 * 80 + 2 * 128 * 80);
    cudaFuncSetAttribute(f16_gemm<64>,  cudaFuncAttributeMaxDynamicSharedMemorySize,
                         2 * 128 * 80 + 2 * 64 * 80);

    float* out_main = (float*)d_out;
    float* out_attn = out_main + (size_t)Lc*Bc*Dc;

    dim3 tb(32, 8);

    // 0) producers: half concat / copies / weight transposes
    concat_kernel<<<(Tc*Bc*Dc + 255)/256, 256>>>(mem, x, p_c);
    half_copy_kernel<<<(Lc*Bc*Dc + 255)/256, 256>>>(x,  p_xr,  Lc*Bc*Dc);
    half_copy_kernel<<<(Tc*Bc*Dc + 255)/256, 256>>>(pe, p_per, Tc*Bc*Dc);
    transpose_kernel<<<dim3(2*HDc/32, Dc/32),  tb>>>(Wkv,  p_WkvT,  Dc, 2*HDc);
    transpose_kernel<<<dim3(HDc/32,   Dc/32),  tb>>>(Wrel, p_WrelT, Dc, HDc);
    transpose_kernel<<<dim3(HDc/32,   Dc/32),  tb>>>(Wq,   p_WqT,   Dc, HDc);
    transpose_kernel<<<dim3(Dc/32,    HDc/32), tb>>>(Wo,   p_WoT,   HDc, Dc);
    transpose_kernel<<<dim3(DFFc/32,  Dc/32),  tb>>>(W1,   p_W1T,   Dc, DFFc);
    transpose_kernel<<<dim3(Dc/32,    DFFc/32),tb>>>(W2,   p_W2T,   DFFc, Dc);

    // 1) kv = c @ Wkv  (half out)
    hg<128>(p_c, p_WkvT, p_kv, Tc*Bc, 2*HDc, Dc, Dc, Dc, 2*HDc,
            1, 1, 0,0,0,0,0,0, nullptr, nullptr, 0, 0, 1);
    // 2) r = pos_emb @ Wrel (half out)
    hg<128>(p_per, p_WrelT, p_r, Tc*Bc, HDc, Dc, Dc, Dc, HDc,
            1, 1, 0,0,0,0,0,0, nullptr, nullptr, 0, 0, 1);
    // 3) qu = x@Wq + u ; qv = x@Wq + v  (dual half outputs, BN=128)
    hg<128>(p_xr, p_WqT, p_qu, Lc*Bc, HDc, Dc, Dc, Dc, HDc,
            1, 1, 0,0,0,0,0,0, pu, nullptr, 0, 0, 1, 0, p_qv, pv);

    // v transpose
    vtrans_kernel<<<dim3(Tc/32, DHc/32, Bc*Hc), tb>>>(p_kv, p_vt);

    // 4) AC = qu @ k^T (half out, mode 1: skip fully-masked tiles)
    hg<128>(p_qu, p_kv, p_Sac, Lc, Tc, DHc, Bc*HDc, Bc*2*HDc, Tc,
            Bc*Hc, Hc,
            (long long)HDc, (long long)DHc,
            (long long)2*HDc, (long long)DHc,
            (long long)Hc*Lc*Tc, (long long)Lc*Tc,
            nullptr, nullptr, 0, 0, 1, 1);
    // 5) BD = qv @ r^T (half out, mode 2: skip tiles the shift never reads)
    hg<128>(p_qv, p_r, p_Sbd, Lc, Tc, DHc, Bc*HDc, Bc*HDc, Tc,
            Bc*Hc, Hc,
            (long long)HDc, (long long)DHc,
            (long long)HDc, (long long)DHc,
            (long long)Hc*Lc*Tc, (long long)Lc*Tc,
            nullptr, nullptr, 0, 0, 1, 2);

    // 6) fused softmax + attn matrix (probs in place, trimmed writes)
    softmax_fused_kernel<<<Lc, 256>>>(p_Sac, p_Sbd, out_attn);

    // 7) vec = probs @ v  (half probs, lda = Tc; BN=64 required by N=64; mode 3 K-clamp)
    hg<64>(p_Sac, p_vt, p_vec, Lc, DHc, Tc, Tc, Tc, Bc*HDc,
           Bc*Hc, Hc,
           (long long)Hc*Lc*Tc, (long long)Lc*Tc,
           (long long)Hc*DHc*Tc, (long long)DHc*Tc,
           (long long)HDc, (long long)DHc,
           nullptr, nullptr, 0, 0, 1, 3);

    // 8) res = x + vec @ Wo  (fp32 out, BN=128)
    hg<128>(p_vec, p_WoT, p_res, Lc*Bc, Dc, HDc, HDc, HDc, Dc,
            1, 1, 0,0,0,0,0,0, nullptr, x, Dc, 0, 0);

    // 9) LN1 (fp32 + half outputs)
    ln_kernel<<<Lc*Bc, 256>>>(p_res, p_out1, p_o1r, g1, b1l);

    // 10) ff1 = relu(out1 @ W1 + b1) (half out)
    hg<128>(p_o1r, p_W1T, p_ff1, Lc*Bc, DFFc, Dc, Dc, Dc, DFFc,
            1, 1, 0,0,0,0,0,0, b1, nullptr, 0, 1, 1);

    // 11) res2 = out1 + ff1 @ W2 + b2 (fp32 out, BN=128)
    hg<128>(p_ff1, p_W2T, p_res2, Lc*Bc, Dc, DFFc, DFFc, DFFc, Dc,
            1, 1, 0,0,0,0,0,0, b2, p_out1, Dc, 0, 0);

    // 12) LN2 -> final output
    ln_kernel<<<Lc*Bc, 256>>>(p_res2, out_main, nullptr, g2, b2l);
}